// round 12
// baseline (speedup 1.0000x reference)
#include <cuda_runtime.h>
#include <cuda_bf16.h>

// BinaryLutLayer: out[i] = (float)(int8) round_half_even( luts_float[i][addr_i] + 0.5 )
// addr_i = sum_b ((x[i][b] != 0) << b); N = 16384 rows, 14 bits, LUT row = 16384 floats.
//
// FINAL — converged at the harness replay floor. Five structural variants
// (smem+BAR 64x256; direct 128x128; +streaming store; canonical; 2 rows/
// thread LDG.128) all time 6.624-6.656 us harness while their cold-cache
// ncu kernel times span 7.46-9.73 us. Warm-run work is ~0.3 us (x and the
// fixed-address gathered LUT lines stay L2-resident across graph replays);
// the remaining ~6.3 us is fixed per-replay launch/wave-ramp overhead. All
// pipes idle in ncu (issue <=3%, DRAM <=5%) -> nothing kernel-side remains.
//
// Chosen shape: 1 thread/row, 128 CTAs x 128 threads (128/148 SMs in one
// wave), 7 front-batched LDG.64 (row stride 56 B, 8B-aligned), one dependent
// 4B gather, one STG. No smem, no barriers, 20 regs. Best cold-start latency
// of all variants (7.68 us ncu).
//
// Correctness: the int8 quantization is recomputed from luts_float (d_in[1],
// unambiguous fp32) because d_in[2]'s device dtype after the harness widened
// jnp.int8 is unknown (indexing it as bytes gave rel_err 0.995 in R2).
// rintf == jnp.round (round-half-even) on bit-identical fp32 -> exact:
// rel_err = 0.0 in every passing round.

#define NUM_BITS 14
#define LUT_SIZE 16384
#define N_OUT    16384
#define TPB      128

__global__ __launch_bounds__(TPB)
void binary_lut_kernel(const float* __restrict__ x,
                       const float* __restrict__ luts_float,
                       float* __restrict__ out)
{
    const int row = blockIdx.x * TPB + threadIdx.x;

    // 14 floats = 7 x float2, 8B-aligned (row stride = 56 B). All 7 loads
    // independent -> front-batched (MLP_p1 = 7), one memory round-trip.
    const float2* __restrict__ p =
        (const float2*)(x + (size_t)row * NUM_BITS);

    float2 v[7];
    #pragma unroll
    for (int j = 0; j < 7; j++)
        v[j] = __ldg(&p[j]);

    int addr = 0;
    #pragma unroll
    for (int j = 0; j < 7; j++) {
        addr |= (v[j].x != 0.0f) ? (1 << (2 * j))     : 0;
        addr |= (v[j].y != 0.0f) ? (1 << (2 * j + 1)) : 0;
    }

    // One dependent 4B gather (row stride = 64 KB in the float LUT).
    const float lv = __ldg(luts_float + (size_t)row * LUT_SIZE + addr);

    // round-half-even (== jnp.round) on bit-identical fp32, int8 cast, float.
    out[row] = (float)(signed char)rintf(lv + 0.5f);
}

extern "C" void kernel_launch(void* const* d_in, const int* in_sizes, int n_in,
                              void* d_out, int out_size)
{
    const float* x          = (const float*)d_in[0];
    const float* luts_float = (const float*)d_in[1];
    // d_in[2] (luts_int) unused: device dtype after harness widening is
    // ambiguous; values are reproduced bit-exactly from luts_float.
    float* out = (float*)d_out;

    binary_lut_kernel<<<N_OUT / TPB, TPB>>>(x, luts_float, out);
}

// round 13
// speedup vs baseline: 1.0505x; 1.0505x over previous
#include <cuda_runtime.h>
#include <cuda_bf16.h>

// BinaryLutLayer: out[i] = (float)(int8) round_half_even( luts_float[i][addr_i] + 0.5 )
// addr_i = sum_b ((x[i][b] != 0) << b); N = 16384 rows, 14 bits, LUT row = 16384 floats.
//
// FINAL — converged at the harness replay floor (6 consecutive rounds flat).
// Six structural variants (smem+BAR 64x256; direct 128x128; +streaming
// store; canonical x2; 2 rows/thread LDG.128) all time 6.624-6.656 us
// harness (one 32 ns timer quantum) while their cold-cache ncu kernel times
// span 7.46-9.73 us with zero correlation to the timed number. Warm-run
// work is ~0.3 us (x and the fixed-address gathered LUT lines stay
// L2-resident across graph replays); the remaining ~6.3 us is fixed
// per-replay launch/wave-ramp overhead. All pipes idle in every profile
// (issue <=3%, DRAM <=5%) -> no kernel-side lever remains.
//
// Shape: 1 thread/row, 128 CTAs x 128 threads (128/148 SMs in one wave),
// 7 front-batched LDG.64 (row stride 56 B, 8B-aligned), one dependent 4B
// gather, one STG. No smem, no barriers, 20 regs. Best cold-start latency
// of all variants.
//
// Correctness: the int8 quantization is recomputed from luts_float (d_in[1],
// unambiguous fp32) because d_in[2]'s device dtype after the harness widened
// jnp.int8 is unknown (indexing it as bytes gave rel_err 0.995 in R2).
// rintf == jnp.round (round-half-even) on bit-identical fp32 -> exact:
// rel_err = 0.0 in every passing round.

#define NUM_BITS 14
#define LUT_SIZE 16384
#define N_OUT    16384
#define TPB      128

__global__ __launch_bounds__(TPB)
void binary_lut_kernel(const float* __restrict__ x,
                       const float* __restrict__ luts_float,
                       float* __restrict__ out)
{
    const int row = blockIdx.x * TPB + threadIdx.x;

    // 14 floats = 7 x float2, 8B-aligned (row stride = 56 B). All 7 loads
    // independent -> front-batched (MLP_p1 = 7), one memory round-trip.
    const float2* __restrict__ p =
        (const float2*)(x + (size_t)row * NUM_BITS);

    float2 v[7];
    #pragma unroll
    for (int j = 0; j < 7; j++)
        v[j] = __ldg(&p[j]);

    int addr = 0;
    #pragma unroll
    for (int j = 0; j < 7; j++) {
        addr |= (v[j].x != 0.0f) ? (1 << (2 * j))     : 0;
        addr |= (v[j].y != 0.0f) ? (1 << (2 * j + 1)) : 0;
    }

    // One dependent 4B gather (row stride = 64 KB in the float LUT).
    const float lv = __ldg(luts_float + (size_t)row * LUT_SIZE + addr);

    // round-half-even (== jnp.round) on bit-identical fp32, int8 cast, float.
    out[row] = (float)(signed char)rintf(lv + 0.5f);
}

extern "C" void kernel_launch(void* const* d_in, const int* in_sizes, int n_in,
                              void* d_out, int out_size)
{
    const float* x          = (const float*)d_in[0];
    const float* luts_float = (const float*)d_in[1];
    // d_in[2] (luts_int) unused: device dtype after harness widening is
    // ambiguous; values are reproduced bit-exactly from luts_float.
    float* out = (float*)d_out;

    binary_lut_kernel<<<N_OUT / TPB, TPB>>>(x, luts_float, out);
}